// round 1
// baseline (speedup 1.0000x reference)
#include <cuda_runtime.h>

// ---------------- problem constants ----------------
#define BATCH   128
#define HH      384
#define WW      384
#define OW      385          // output width/height for k=2 and k=4
#define SH      43           // output rows per strip
#define STRIPS  9            // ceil(385/43)
#define NPART   (STRIPS*BATCH)
#define NTHREADS 416         // 13 warps; threads 0..384 are "columns", 385..415 idle

// ---------------- shared memory layout (floats) ----------------
// padded raw row: width 384 + 8 (3 zero pad each side, +1 slack), col c at index c+4
#define OFF_X   0
#define OFF_Y   392
#define OFF_H2  784                         // 5 moments * 6-row ring * 385
#define OFF_H4  (OFF_H2 + 5*6*385)          // 5 * 7 * 385
#define OFF_H7  (OFF_H4 + 5*7*385)          // 5 * 8 * 385
#define OFF_RED (OFF_H7 + 5*8*385)          // 13 warps * 5 accumulators
#define SMEM_FLOATS (OFF_RED + 13*5)
#define SMEM_BYTES  (SMEM_FLOATS * 4)

// per-(block) partial sums: [S1, S2, S4, S7, L1]
__device__ float g_part[NPART * 5];

// Scaled SSIM from raw window sums. n = k*k, c1 = C1*n^2, c2 = C2*n^2.
__device__ __forceinline__ float ssim_scaled(float Sx, float Sy, float Sxx, float Syy,
                                             float Sxy, float n, float c1, float c2)
{
    float t  = Sx * Sy;
    float A1 = fmaf(2.f, t, c1);                 // 2*Sx*Sy + C1*n^2
    float u  = fmaf(n, Sxy, -t);                 // n*Sxy - Sx*Sy
    float A2 = fmaf(2.f, u, c2);                 // 2*(n*Sxy - SxSy) + C2*n^2
    float p  = Sx * Sx;
    float pq = fmaf(Sy, Sy, p);                  // Sx^2 + Sy^2
    float B1 = pq + c1;
    float w  = fmaf(n, Sxx + Syy, -pq);          // n*(Sxx+Syy) - Sx^2 - Sy^2
    float B2 = w + c2;
    return __fdividef(A1 * A2, B1 * B2);
}

__global__ __launch_bounds__(NTHREADS)
void msssim_main_kernel(const float* __restrict__ X,
                        const float* __restrict__ Y,
                        const float* __restrict__ DR)
{
    extern __shared__ float sm[];
    const int tid = threadIdx.x;
    const int b   = blockIdx.y;
    const int i0  = blockIdx.x * SH;
    const int i1  = min(i0 + SH, OW);      // output rows [i0, i1) for k=2/4 (k=7/1 capped at 384)
    const int A   = max(i0 - 3, 0);        // first row participating in this strip's windows
    const int i1k = min(i1, HH);

    const float dr = DR[b];
    const float C1 = (0.01f * dr) * (0.01f * dr);
    const float C2 = (0.03f * dr) * (0.03f * dr);
    const float c1_2 = C1 * 16.f,   c2_2 = C2 * 16.f;     // n=4
    const float c1_4 = C1 * 256.f,  c2_4 = C2 * 256.f;    // n=16
    const float c1_7 = C1 * 2401.f, c2_7 = C2 * 2401.f;   // n=49

    // zero the horizontal pad cells once
    if (tid < 4) {
        sm[OFF_X + tid] = 0.f;        sm[OFF_Y + tid] = 0.f;
        sm[OFF_X + 388 + tid] = 0.f;  sm[OFF_Y + 388 + tid] = 0.f;
    }

    // vertical running sums (registers): [Sx, Sy, Sxx, Syy, Sxy]
    float v2[5] = {0,0,0,0,0}, v4[5] = {0,0,0,0,0}, v7[5] = {0,0,0,0,0};
    float acc1 = 0.f, acc2 = 0.f, acc4 = 0.f, acc7 = 0.f, accL = 0.f;

    const size_t base = (size_t)b * (HH * WW);
    const int  j       = tid;
    const bool colMain = (tid < 384);     // real image columns
    const bool colExt  = (tid <= 384);    // extended column for 385-wide outputs

    for (int i = i0 - 6; i < i1; ++i) {
        const int  r  = i + 3;                       // row whose hsums we produce this iter
        const bool rv = (r >= 0) && (r < HH);

        __syncthreads();                              // WAR: prior iter's readers done
        float xv = 0.f, yv = 0.f;
        if (colMain && rv) {
            xv = X[base + (size_t)r * WW + j];
            yv = Y[base + (size_t)r * WW + j];
            sm[OFF_X + 4 + j] = xv;
            sm[OFF_Y + 4 + j] = yv;
        }
        __syncthreads();                              // RAW: row visible

        // k=1 SSIM contribution for row r (vx=vy=vxy=0 -> S=(2xy+C1)/(x^2+y^2+C1))
        if (colMain && rv && r >= i0 && r < i1k) {
            float t  = xv * yv;
            float a1 = fmaf(2.f, t, C1);
            float b1 = fmaf(xv, xv, fmaf(yv, yv, C1));
            acc1 += __fdividef(a1, b1);
        }

        // -------- nested horizontal window sums for row r --------
        float h7x = 0.f, h7y = 0.f, h7xx = 0.f, h7yy = 0.f, h7xy = 0.f;
        if (colExt && rv) {
            const float xm3 = sm[OFF_X + j + 1], ym3 = sm[OFF_Y + j + 1];
            const float xm2 = sm[OFF_X + j + 2], ym2 = sm[OFF_Y + j + 2];
            const float xm1 = sm[OFF_X + j + 3], ym1 = sm[OFF_Y + j + 3];
            const float x0  = sm[OFF_X + j + 4], y0  = sm[OFF_Y + j + 4];
            const float xp1 = sm[OFF_X + j + 5], yp1 = sm[OFF_Y + j + 5];
            const float xp2 = sm[OFF_X + j + 6], yp2 = sm[OFF_Y + j + 6];
            const float xp3 = sm[OFF_X + j + 7], yp3 = sm[OFF_Y + j + 7];

            // k=2 window: cols {j-1, j}
            float h2x  = xm1 + x0;
            float h2y  = ym1 + y0;
            float h2xx = fmaf(xm1, xm1, x0 * x0);
            float h2yy = fmaf(ym1, ym1, y0 * y0);
            float h2xy = fmaf(xm1, ym1, x0 * y0);
            // k=4 adds cols {j-2, j+1}
            float h4x  = h2x + xm2 + xp1;
            float h4y  = h2y + ym2 + yp1;
            float h4xx = h2xx + fmaf(xm2, xm2, xp1 * xp1);
            float h4yy = h2yy + fmaf(ym2, ym2, yp1 * yp1);
            float h4xy = h2xy + fmaf(xm2, ym2, xp1 * yp1);
            // k=7 adds cols {j-3, j+2, j+3}
            h7x  = h4x + xm3 + xp2 + xp3;
            h7y  = h4y + ym3 + yp2 + yp3;
            h7xx = h4xx + fmaf(xm3, xm3, fmaf(xp2, xp2, xp3 * xp3));
            h7yy = h4yy + fmaf(ym3, ym3, fmaf(yp2, yp2, yp3 * yp3));
            h7xy = h4xy + fmaf(xm3, ym3, fmaf(xp2, yp2, xp3 * yp3));

            const int sl2 = r % 6, sl4 = r % 7, sl7 = r & 7;
            sm[OFF_H2 + (0*6 + sl2)*385 + j] = h2x;
            sm[OFF_H2 + (1*6 + sl2)*385 + j] = h2y;
            sm[OFF_H2 + (2*6 + sl2)*385 + j] = h2xx;
            sm[OFF_H2 + (3*6 + sl2)*385 + j] = h2yy;
            sm[OFF_H2 + (4*6 + sl2)*385 + j] = h2xy;
            sm[OFF_H4 + (0*7 + sl4)*385 + j] = h4x;
            sm[OFF_H4 + (1*7 + sl4)*385 + j] = h4y;
            sm[OFF_H4 + (2*7 + sl4)*385 + j] = h4xx;
            sm[OFF_H4 + (3*7 + sl4)*385 + j] = h4yy;
            sm[OFF_H4 + (4*7 + sl4)*385 + j] = h4xy;
            sm[OFF_H7 + (0*8 + sl7)*385 + j] = h7x;
            sm[OFF_H7 + (1*8 + sl7)*385 + j] = h7y;
            sm[OFF_H7 + (2*8 + sl7)*385 + j] = h7xx;
            sm[OFF_H7 + (3*8 + sl7)*385 + j] = h7yy;
            sm[OFF_H7 + (4*8 + sl7)*385 + j] = h7xy;

            // k=7 add of row r (our own registers; no readback needed)
            v7[0] += h7x; v7[1] += h7y; v7[2] += h7xx; v7[3] += h7yy; v7[4] += h7xy;
        }

        if (colExt) {
            int t;
            // k=2: window rows [i-1, i] -> add row i, sub row i-2
            t = i;
            if (t >= A && t < HH) {
                int s = t % 6;
                #pragma unroll
                for (int q = 0; q < 5; ++q) v2[q] += sm[OFF_H2 + (q*6 + s)*385 + j];
            }
            t = i - 2;
            if (t >= A) {                       // t <= i1-3 <= 382 < 384 always
                int s = t % 6;
                #pragma unroll
                for (int q = 0; q < 5; ++q) v2[q] -= sm[OFF_H2 + (q*6 + s)*385 + j];
            }
            // k=4: window rows [i-2, i+1] -> add row i+1, sub row i-3
            t = i + 1;
            if (t >= A && t < HH) {
                int s = t % 7;
                #pragma unroll
                for (int q = 0; q < 5; ++q) v4[q] += sm[OFF_H4 + (q*7 + s)*385 + j];
            }
            t = i - 3;
            if (t >= A) {
                int s = t % 7;
                #pragma unroll
                for (int q = 0; q < 5; ++q) v4[q] -= sm[OFF_H4 + (q*7 + s)*385 + j];
            }
            // k=7: window rows [i-3, i+3] -> add row i+3 (done above), sub row i-4
            t = i - 4;
            if (t >= A) {
                int s = t & 7;
                #pragma unroll
                for (int q = 0; q < 5; ++q) v7[q] -= sm[OFF_H7 + (q*8 + s)*385 + j];
            }

            // -------- emit output row i --------
            if (i >= i0) {
                acc2 += ssim_scaled(v2[0], v2[1], v2[2], v2[3], v2[4], 4.f,  c1_2, c2_2);
                acc4 += ssim_scaled(v4[0], v4[1], v4[2], v4[3], v4[4], 16.f, c1_4, c2_4);
                if (i < HH && colMain) {
                    acc7 += ssim_scaled(v7[0], v7[1], v7[2], v7[3], v7[4], 49.f, c1_7, c2_7);
                    accL += fabsf(v7[0] - v7[1]);   // 49 * |box7(X)-box7(Y)|
                }
            }
        }
    }

    // ---------------- deterministic block reduction ----------------
    #pragma unroll
    for (int o = 16; o > 0; o >>= 1) {
        acc1 += __shfl_down_sync(0xFFFFFFFFu, acc1, o);
        acc2 += __shfl_down_sync(0xFFFFFFFFu, acc2, o);
        acc4 += __shfl_down_sync(0xFFFFFFFFu, acc4, o);
        acc7 += __shfl_down_sync(0xFFFFFFFFu, acc7, o);
        accL += __shfl_down_sync(0xFFFFFFFFu, accL, o);
    }
    __syncthreads();   // rings no longer needed; reuse OFF_RED region safely
    const int w = tid >> 5, lane = tid & 31;
    if (lane == 0) {
        sm[OFF_RED + w*5 + 0] = acc1;
        sm[OFF_RED + w*5 + 1] = acc2;
        sm[OFF_RED + w*5 + 2] = acc4;
        sm[OFF_RED + w*5 + 3] = acc7;
        sm[OFF_RED + w*5 + 4] = accL;
    }
    __syncthreads();
    if (tid == 0) {
        float s0 = 0.f, s1 = 0.f, s2 = 0.f, s3 = 0.f, s4 = 0.f;
        for (int ww = 0; ww < 13; ++ww) {
            s0 += sm[OFF_RED + ww*5 + 0];
            s1 += sm[OFF_RED + ww*5 + 1];
            s2 += sm[OFF_RED + ww*5 + 2];
            s3 += sm[OFF_RED + ww*5 + 3];
            s4 += sm[OFF_RED + ww*5 + 4];
        }
        const int pb = (b * STRIPS + blockIdx.x) * 5;
        g_part[pb + 0] = s0;
        g_part[pb + 1] = s1;
        g_part[pb + 2] = s2;
        g_part[pb + 3] = s3;
        g_part[pb + 4] = s4;
    }
}

__global__ void msssim_reduce_kernel(float* __restrict__ out)
{
    __shared__ double red[256][5];
    double a0 = 0, a1 = 0, a2 = 0, a3 = 0, a4 = 0;
    for (int idx = threadIdx.x; idx < NPART; idx += 256) {
        a0 += (double)g_part[idx*5 + 0];
        a1 += (double)g_part[idx*5 + 1];
        a2 += (double)g_part[idx*5 + 2];
        a3 += (double)g_part[idx*5 + 3];
        a4 += (double)g_part[idx*5 + 4];
    }
    red[threadIdx.x][0] = a0; red[threadIdx.x][1] = a1; red[threadIdx.x][2] = a2;
    red[threadIdx.x][3] = a3; red[threadIdx.x][4] = a4;
    __syncthreads();
    for (int s = 128; s > 0; s >>= 1) {
        if (threadIdx.x < s) {
            #pragma unroll
            for (int q = 0; q < 5; ++q) red[threadIdx.x][q] += red[threadIdx.x + s][q];
        }
        __syncthreads();
    }
    if (threadIdx.x == 0) {
        const double n384 = (double)BATCH * 384.0 * 384.0;
        const double n385 = (double)BATCH * 385.0 * 385.0;
        double m1 = red[0][0] / n384;
        double m2 = red[0][1] / n385;
        double m4 = red[0][2] / n385;
        double m7 = red[0][3] / n384;
        double l1 = red[0][4] / (49.0 * n384);
        double loss = 0.84 * (1.0 - m1 * m2 * m4 * m7) + 0.16 * l1;
        out[0] = (float)loss;
    }
}

extern "C" void kernel_launch(void* const* d_in, const int* in_sizes, int n_in,
                              void* d_out, int out_size)
{
    (void)in_sizes; (void)n_in; (void)out_size;
    const float* X  = (const float*)d_in[0];
    const float* Y  = (const float*)d_in[1];
    const float* DR = (const float*)d_in[2];

    cudaFuncSetAttribute(msssim_main_kernel,
                         cudaFuncAttributeMaxDynamicSharedMemorySize, SMEM_BYTES);

    dim3 grid(STRIPS, BATCH);
    msssim_main_kernel<<<grid, NTHREADS, SMEM_BYTES>>>(X, Y, DR);
    msssim_reduce_kernel<<<1, 256>>>((float*)d_out);
}

// round 2
// speedup vs baseline: 1.5181x; 1.5181x over previous
#include <cuda_runtime.h>

typedef unsigned long long ull;

// ---------------- problem constants ----------------
#define BATCH   128
#define HH      384
#define WW      384
#define OW      385          // output width/height for k=2 and k=4
#define SH      49           // output rows per strip
#define STRIPS  8            // ceil(385/49)
#define NPART   (STRIPS*BATCH)
#define NTHREADS 416         // 13 warps; threads 0..384 are "columns"

// shared memory (bytes): ull region + float region
// ull: rowp 2*400  + rings s/q (6+6+7+7+8+8)*385 = 16970 ull
// flt: rings xy (6+7+8)*385 + 65 red = 8150 floats
#define SMEM_BYTES (16970*8 + 8150*4)

__device__ float g_part[NPART * 5];

// ---------------- packed f32x2 helpers ----------------
__device__ __forceinline__ ull f2pack(float lo, float hi) {
    ull r; asm("mov.b64 %0,{%1,%2};" : "=l"(r) : "f"(lo), "f"(hi)); return r;
}
__device__ __forceinline__ void f2unpack(ull v, float& lo, float& hi) {
    asm("mov.b64 {%0,%1},%2;" : "=f"(lo), "=f"(hi) : "l"(v));
}
__device__ __forceinline__ ull f2add(ull a, ull b) {
    ull r; asm("add.rn.f32x2 %0,%1,%2;" : "=l"(r) : "l"(a), "l"(b)); return r;
}
__device__ __forceinline__ ull f2mul(ull a, ull b) {
    ull r; asm("mul.rn.f32x2 %0,%1,%2;" : "=l"(r) : "l"(a), "l"(b)); return r;
}
__device__ __forceinline__ ull f2fma(ull a, ull b, ull c) {
    ull r; asm("fma.rn.f32x2 %0,%1,%2,%3;" : "=l"(r) : "l"(a), "l"(b), "l"(c)); return r;
}
#define F2NEG1 0xBF800000BF800000ULL   // (-1.0f, -1.0f)

// Scaled SSIM from raw window sums. n = k*k, c1 = C1*n^2, c2 = C2*n^2.
__device__ __forceinline__ float ssim_scaled(float Sx, float Sy, float Sxx, float Syy,
                                             float Sxy, float n, float c1, float c2)
{
    float t  = Sx * Sy;
    float A1 = fmaf(2.f, t, c1);                 // 2*Sx*Sy + C1*n^2
    float u  = fmaf(n, Sxy, -t);                 // n*Sxy - Sx*Sy
    float A2 = fmaf(2.f, u, c2);
    float p  = Sx * Sx;
    float pq = fmaf(Sy, Sy, p);                  // Sx^2 + Sy^2
    float B1 = pq + c1;
    float w  = fmaf(n, Sxx + Syy, -pq);          // n*(Sxx+Syy) - Sx^2 - Sy^2
    float B2 = w + c2;
    return __fdividef(A1 * A2, B1 * B2);
}

__global__ __launch_bounds__(NTHREADS)
void msssim_main_kernel(const float* __restrict__ X,
                        const float* __restrict__ Y,
                        const float* __restrict__ DR)
{
    extern __shared__ ull sm8[];
    ull*  rowp = sm8;                 // [2][400] packed (x,y); col c at idx c+4
    ull*  r2s  = rowp + 2*400;        // rings: packed (Sx,Sy)
    ull*  r2q  = r2s + 6*385;         //        packed (Sxx,Syy)
    ull*  r4s  = r2q + 6*385;
    ull*  r4q  = r4s + 7*385;
    ull*  r7s  = r4q + 7*385;
    ull*  r7q  = r7s + 8*385;
    float* r2xy = (float*)(r7q + 8*385);  // scalar Sxy rings
    float* r4xy = r2xy + 6*385;
    float* r7xy = r4xy + 7*385;
    float* red  = r7xy + 8*385;           // 13 warps * 5

    const int tid = threadIdx.x;
    const int b   = blockIdx.y;
    const int i0  = blockIdx.x * SH;
    const int i1  = min(i0 + SH, OW);
    const int A   = max(i0 - 3, 0);
    const int i1k = min(i1, HH);

    const float dr = DR[b];
    const float C1 = (0.01f * dr) * (0.01f * dr);
    const float C2 = (0.03f * dr) * (0.03f * dr);
    const float c1_2 = C1 * 16.f,   c2_2 = C2 * 16.f;     // n=4
    const float c1_4 = C1 * 256.f,  c2_4 = C2 * 256.f;    // n=16
    const float c1_7 = C1 * 2401.f, c2_7 = C2 * 2401.f;   // n=49

    // zero the horizontal pad cells of both row buffers (idx 0..3, 388..391)
    if (tid < 8) {
        int idx = (tid < 4) ? tid : (384 + tid);
        rowp[idx] = 0ULL; rowp[400 + idx] = 0ULL;
    }

    // vertical running sums: packed (Sx,Sy), packed (Sxx,Syy), scalar Sxy
    ull v2s = 0, v2q = 0, v4s = 0, v4q = 0, v7s = 0, v7q = 0;
    float v2xy = 0.f, v4xy = 0.f, v7xy = 0.f;
    float acc1 = 0.f, acc2 = 0.f, acc4 = 0.f, acc7 = 0.f, accL = 0.f;

    const size_t base = (size_t)b * (HH * WW);
    const int  j       = tid;
    const bool colMain = (tid < 384);
    const bool colExt  = (tid <= 384);

    // prologue: prefetch row for the first iteration (r = i0-3)
    float xcur = 0.f, ycur = 0.f;
    {
        int rp = i0 - 3;
        if (colMain && rp >= 0 && rp < HH) {
            xcur = X[base + (size_t)rp * WW + j];
            ycur = Y[base + (size_t)rp * WW + j];
        }
    }

    for (int i = i0 - 6; i < i1; ++i) {
        const int  r  = i + 3;
        const bool rv = (r >= 0) && (r < HH);

        // prefetch next row (consumed next iteration) — hides gmem latency
        float xn = 0.f, yn = 0.f;
        {
            int rn = r + 1;
            if (colMain && rn >= 0 && rn < HH) {
                xn = X[base + (size_t)rn * WW + j];
                yn = Y[base + (size_t)rn * WW + j];
            }
        }

        // store current row (packed) into parity buffer
        if (colMain && rv)
            rowp[(r & 1) * 400 + 4 + j] = f2pack(xcur, ycur);

        __syncthreads();   // row r visible; WAR on other parity buffer safe

        // k=1 SSIM for row r
        if (colMain && rv && r >= i0 && r < i1k) {
            float t  = xcur * ycur;
            float a1 = fmaf(2.f, t, C1);
            float b1 = fmaf(xcur, xcur, fmaf(ycur, ycur, C1));
            acc1 += __fdividef(a1, b1);
        }

        // -------- nested horizontal window sums for row r (packed) --------
        if (colExt && rv) {
            const ull* rb = rowp + (r & 1) * 400 + (j + 1);
            ull p0 = rb[0], p1 = rb[1], p2 = rb[2], p3 = rb[3],
                p4 = rb[4], p5 = rb[5], p6 = rb[6];
            float x0,y0,x1,y1,x2,y2,x3,y3,x4,y4,x5,y5,x6,y6;
            f2unpack(p0,x0,y0); f2unpack(p1,x1,y1); f2unpack(p2,x2,y2);
            f2unpack(p3,x3,y3); f2unpack(p4,x4,y4); f2unpack(p5,x5,y5);
            f2unpack(p6,x6,y6);

            // k=2: cols {j-1, j} = p2,p3
            ull  s2 = f2add(p2, p3);
            ull  q2 = f2fma(p2, p2, f2mul(p3, p3));
            float w2xy = fmaf(x2, y2, x3 * y3);
            // k=4 adds p1,p4
            ull  s4 = f2add(f2add(s2, p1), p4);
            ull  q4 = f2fma(p1, p1, f2fma(p4, p4, q2));
            float w4xy = fmaf(x1, y1, fmaf(x4, y4, w2xy));
            // k=7 adds p0,p5,p6
            ull  s7 = f2add(f2add(f2add(s4, p0), p5), p6);
            ull  q7 = f2fma(p0, p0, f2fma(p5, p5, f2fma(p6, p6, q4)));
            float w7xy = fmaf(x0, y0, fmaf(x5, y5, fmaf(x6, y6, w4xy)));

            const int sl2 = r % 6, sl4 = r % 7, sl7 = r & 7;
            r2s[sl2*385 + j] = s2;  r2q[sl2*385 + j] = q2;  r2xy[sl2*385 + j] = w2xy;
            r4s[sl4*385 + j] = s4;  r4q[sl4*385 + j] = q4;  r4xy[sl4*385 + j] = w4xy;
            r7s[sl7*385 + j] = s7;  r7q[sl7*385 + j] = q7;  r7xy[sl7*385 + j] = w7xy;

            // k=7 vertical add of row r (registers, no readback)
            v7s = f2add(v7s, s7); v7q = f2add(v7q, q7); v7xy += w7xy;
        }

        // -------- vertical slides (all ring traffic is thread-private) --------
        if (colExt) {
            int t;
            // k=2: add row i, sub row i-2
            t = i;
            if (t >= A && t < HH) {
                int s = t % 6;
                v2s = f2add(v2s, r2s[s*385 + j]);
                v2q = f2add(v2q, r2q[s*385 + j]);
                v2xy += r2xy[s*385 + j];
            }
            t = i - 2;
            if (t >= A) {
                int s = t % 6;
                v2s = f2fma(r2s[s*385 + j], F2NEG1, v2s);
                v2q = f2fma(r2q[s*385 + j], F2NEG1, v2q);
                v2xy -= r2xy[s*385 + j];
            }
            // k=4: add row i+1, sub row i-3
            t = i + 1;
            if (t >= A && t < HH) {
                int s = t % 7;
                v4s = f2add(v4s, r4s[s*385 + j]);
                v4q = f2add(v4q, r4q[s*385 + j]);
                v4xy += r4xy[s*385 + j];
            }
            t = i - 3;
            if (t >= A) {
                int s = t % 7;
                v4s = f2fma(r4s[s*385 + j], F2NEG1, v4s);
                v4q = f2fma(r4q[s*385 + j], F2NEG1, v4q);
                v4xy -= r4xy[s*385 + j];
            }
            // k=7: add row i+3 (done above), sub row i-4
            t = i - 4;
            if (t >= A) {
                int s = t & 7;
                v7s = f2fma(r7s[s*385 + j], F2NEG1, v7s);
                v7q = f2fma(r7q[s*385 + j], F2NEG1, v7q);
                v7xy -= r7xy[s*385 + j];
            }

            // -------- emit output row i --------
            if (i >= i0) {
                float Sx, Sy, Sxx, Syy;
                f2unpack(v2s, Sx, Sy); f2unpack(v2q, Sxx, Syy);
                acc2 += ssim_scaled(Sx, Sy, Sxx, Syy, v2xy, 4.f,  c1_2, c2_2);
                f2unpack(v4s, Sx, Sy); f2unpack(v4q, Sxx, Syy);
                acc4 += ssim_scaled(Sx, Sy, Sxx, Syy, v4xy, 16.f, c1_4, c2_4);
                if (i < HH && colMain) {
                    f2unpack(v7s, Sx, Sy); f2unpack(v7q, Sxx, Syy);
                    acc7 += ssim_scaled(Sx, Sy, Sxx, Syy, v7xy, 49.f, c1_7, c2_7);
                    accL += fabsf(Sx - Sy);   // 49 * |box7(X)-box7(Y)|
                }
            }
        }

        xcur = xn; ycur = yn;
    }

    // ---------------- deterministic block reduction ----------------
    #pragma unroll
    for (int o = 16; o > 0; o >>= 1) {
        acc1 += __shfl_down_sync(0xFFFFFFFFu, acc1, o);
        acc2 += __shfl_down_sync(0xFFFFFFFFu, acc2, o);
        acc4 += __shfl_down_sync(0xFFFFFFFFu, acc4, o);
        acc7 += __shfl_down_sync(0xFFFFFFFFu, acc7, o);
        accL += __shfl_down_sync(0xFFFFFFFFu, accL, o);
    }
    const int w = tid >> 5, lane = tid & 31;
    if (lane == 0) {
        red[w*5 + 0] = acc1; red[w*5 + 1] = acc2; red[w*5 + 2] = acc4;
        red[w*5 + 3] = acc7; red[w*5 + 4] = accL;
    }
    __syncthreads();
    if (tid == 0) {
        float s0 = 0.f, s1 = 0.f, s2 = 0.f, s3 = 0.f, s4 = 0.f;
        for (int ww = 0; ww < 13; ++ww) {
            s0 += red[ww*5 + 0]; s1 += red[ww*5 + 1]; s2 += red[ww*5 + 2];
            s3 += red[ww*5 + 3]; s4 += red[ww*5 + 4];
        }
        const int pb = (b * STRIPS + blockIdx.x) * 5;
        g_part[pb + 0] = s0; g_part[pb + 1] = s1; g_part[pb + 2] = s2;
        g_part[pb + 3] = s3; g_part[pb + 4] = s4;
    }
}

__global__ void msssim_reduce_kernel(float* __restrict__ out)
{
    __shared__ double red[256][5];
    double a0 = 0, a1 = 0, a2 = 0, a3 = 0, a4 = 0;
    for (int idx = threadIdx.x; idx < NPART; idx += 256) {
        a0 += (double)g_part[idx*5 + 0];
        a1 += (double)g_part[idx*5 + 1];
        a2 += (double)g_part[idx*5 + 2];
        a3 += (double)g_part[idx*5 + 3];
        a4 += (double)g_part[idx*5 + 4];
    }
    red[threadIdx.x][0] = a0; red[threadIdx.x][1] = a1; red[threadIdx.x][2] = a2;
    red[threadIdx.x][3] = a3; red[threadIdx.x][4] = a4;
    __syncthreads();
    for (int s = 128; s > 0; s >>= 1) {
        if (threadIdx.x < s) {
            #pragma unroll
            for (int q = 0; q < 5; ++q) red[threadIdx.x][q] += red[threadIdx.x + s][q];
        }
        __syncthreads();
    }
    if (threadIdx.x == 0) {
        const double n384 = (double)BATCH * 384.0 * 384.0;
        const double n385 = (double)BATCH * 385.0 * 385.0;
        double m1 = red[0][0] / n384;
        double m2 = red[0][1] / n385;
        double m4 = red[0][2] / n385;
        double m7 = red[0][3] / n384;
        double l1 = red[0][4] / (49.0 * n384);
        double loss = 0.84 * (1.0 - m1 * m2 * m4 * m7) + 0.16 * l1;
        out[0] = (float)loss;
    }
}

extern "C" void kernel_launch(void* const* d_in, const int* in_sizes, int n_in,
                              void* d_out, int out_size)
{
    (void)in_sizes; (void)n_in; (void)out_size;
    const float* X  = (const float*)d_in[0];
    const float* Y  = (const float*)d_in[1];
    const float* DR = (const float*)d_in[2];

    cudaFuncSetAttribute(msssim_main_kernel,
                         cudaFuncAttributeMaxDynamicSharedMemorySize, SMEM_BYTES);

    dim3 grid(STRIPS, BATCH);
    msssim_main_kernel<<<grid, NTHREADS, SMEM_BYTES>>>(X, Y, DR);
    msssim_reduce_kernel<<<1, 256>>>((float*)d_out);
}